// round 1
// baseline (speedup 1.0000x reference)
#include <cuda_runtime.h>
#include <cstdint>

#define BB      16
#define CC      30
#define TOPK    200
#define MAXDET  100
#define CAP     4096
#define NBIN    256
#define SAMP    16
#define SUFF_TARGET 48

// ---------------- scratch (device globals; no allocations) ----------------
__device__ int d_hist[BB * CC * NBIN];          // sampled histograms
__device__ int d_binlo[BB * CC];                // collection threshold bin
__device__ int d_candcnt[BB * CC];              // collected counts
__device__ unsigned long long d_cand[(size_t)BB * CC * CAP];   // candidate keys
__device__ float d_nms_s[BB * CC * TOPK];       // post-NMS scores (-inf suppressed)
__device__ int   d_nms_i[BB * CC * TOPK];       // original anchor index
__device__ unsigned long long d_top[BB * 1024]; // merge stage-1 output

// ---------------- helpers ----------------
__device__ __forceinline__ void bitonic_sort_desc(unsigned long long* s, int n,
                                                  int tid, int nt) {
    for (int k = 2; k <= n; k <<= 1) {
        for (int j = k >> 1; j > 0; j >>= 1) {
            for (int t = tid; t < n; t += nt) {
                int ixj = t ^ j;
                if (ixj > t) {
                    unsigned long long a = s[t], b = s[ixj];
                    bool up = (t & k) == 0;            // descending sort
                    bool sw = up ? (a < b) : (a > b);
                    if (sw) { s[t] = b; s[ixj] = a; }
                }
            }
            __syncthreads();
        }
    }
}

__device__ __forceinline__ float neg_inf_f() { return __int_as_float(0xff800000); }

// ---------------- kernels ----------------
__global__ void k_zero() {
    int t = blockIdx.x * blockDim.x + threadIdx.x;
    int stride = gridDim.x * blockDim.x;
    for (int i = t; i < BB * CC * NBIN; i += stride) d_hist[i] = 0;
    for (int i = t; i < BB * CC; i += stride) d_candcnt[i] = 0;
}

// Sampled histogram: every SAMP-th anchor row, all classes (contiguous 120B rows).
__global__ __launch_bounds__(512) void k_hist(const float* __restrict__ cls, int N) {
    __shared__ int h[CC * NBIN];
    int b = blockIdx.y, tid = threadIdx.x;
    for (int t = tid; t < CC * NBIN; t += blockDim.x) h[t] = 0;
    __syncthreads();

    int nS = (N + SAMP - 1) / SAMP;
    int per = (nS + gridDim.x - 1) / gridDim.x;
    int r0 = blockIdx.x * per;
    int r1 = min(nS, r0 + per);
    const float* base = cls + (size_t)b * N * CC;
    for (long e = (long)r0 * CC + tid; e < (long)r1 * CC; e += blockDim.x) {
        int r = (int)(e / CC);
        int c = (int)(e - (long)r * CC);
        float v = base[(size_t)r * SAMP * CC + c];
        if (v > 0.01f) {
            int bin = (int)(v * 256.0f);
            bin = bin > 255 ? 255 : bin;     // bin >= 0 since v > 0.01
            atomicAdd(&h[c * NBIN + bin], 1);
        }
    }
    __syncthreads();
    for (int t = tid; t < CC * NBIN; t += blockDim.x) {
        int v = h[t];
        if (v) atomicAdd(&d_hist[b * CC * NBIN + t], v);
    }
}

__global__ void k_thresh() {
    int pc = blockIdx.x * blockDim.x + threadIdx.x;
    if (pc >= BB * CC) return;
    int acc = 0, lo = 0;
    for (int s = NBIN - 1; s >= 0; s--) {
        acc += d_hist[pc * NBIN + s];
        if (acc >= SUFF_TARGET) { lo = s; break; }
    }
    d_binlo[pc] = lo;
}

// Full contiguous pass: collect candidates >= threshold bin.
__global__ __launch_bounds__(512) void k_collect(const float* __restrict__ cls, int N) {
    __shared__ float slo[CC];
    __shared__ float sminlo;
    int b = blockIdx.y, tid = threadIdx.x;
    if (tid < CC) slo[tid] = (float)d_binlo[b * CC + tid];
    __syncthreads();
    if (tid == 0) {
        float mn = 1e9f;
        for (int c = 0; c < CC; c++) mn = fminf(mn, slo[c]);
        sminlo = mn;
    }
    __syncthreads();
    float minlo = sminlo;

    int rows = (((N + (int)gridDim.x - 1) / (int)gridDim.x) + 1) & ~1;  // even
    int r0 = blockIdx.x * rows;
    int r1 = min(N, r0 + rows);
    if (r0 >= r1) return;

    size_t ibase = (size_t)b * N * CC;
    long e0 = (long)r0 * CC, e1 = (long)r1 * CC;

    bool vec_ok = (((ibase + (size_t)e0) & 3) == 0);
    long nv = vec_ok ? ((e1 - e0) >> 2) : 0;
    const float4* p4 = reinterpret_cast<const float4*>(cls + ibase + e0);

    for (long v = tid; v < nv; v += blockDim.x) {
        float4 q = p4[v];
        long e = e0 + (v << 2);
        float vals[4] = {q.x, q.y, q.z, q.w};
        #pragma unroll
        for (int j = 0; j < 4; j++) {
            float val = vals[j];
            if (val > 0.01f) {
                float prod = val * 256.0f;
                if (prod >= minlo) {                     // fast reject
                    long ee = e + j;
                    int c = (int)(ee % CC);
                    if (prod >= slo[c]) {
                        int i = (int)(ee / CC);
                        int pcc = b * CC + c;
                        int p = atomicAdd(&d_candcnt[pcc], 1);
                        if (p < CAP)
                            d_cand[(size_t)pcc * CAP + p] =
                                ((unsigned long long)__float_as_uint(val) << 32) |
                                (unsigned long long)(unsigned)(~(unsigned)i);
                    }
                }
            }
        }
    }
    // scalar tail (and full range if not vectorizable)
    long estart = e0 + nv * 4;
    for (long ee = estart + tid; ee < e1; ee += blockDim.x) {
        float val = cls[ibase + ee];
        if (val > 0.01f) {
            float prod = val * 256.0f;
            if (prod >= minlo) {
                int c = (int)(ee % CC);
                if (prod >= slo[c]) {
                    int i = (int)(ee / CC);
                    int pcc = b * CC + c;
                    int p = atomicAdd(&d_candcnt[pcc], 1);
                    if (p < CAP)
                        d_cand[(size_t)pcc * CAP + p] =
                            ((unsigned long long)__float_as_uint(val) << 32) |
                            (unsigned long long)(unsigned)(~(unsigned)i);
                }
            }
        }
    }
}

// Per (b,c): exact top-200 (sort collected), then greedy NMS identical to reference.
__global__ __launch_bounds__(256) void k_nms(const float* __restrict__ cls,
                                             const float* __restrict__ boxes, int N) {
    __shared__ unsigned long long keys[CAP];
    __shared__ float sx1[TOPK], sy1[TOPK], sx2[TOPK], sy2[TOPK], sar[TOPK];
    __shared__ unsigned long long smask[TOPK * 4];
    __shared__ unsigned long long skeep[4];
    __shared__ int fh[NBIN];
    __shared__ int s_flo, s_fc;

    int pc = blockIdx.x;
    int b = pc / CC, c = pc % CC;
    int tid = threadIdx.x;

    int cnt = d_candcnt[pc];
    int lo = d_binlo[pc];
    bool good = (cnt <= CAP) && (cnt >= TOPK || lo == 0);

    int n;  // sort size (power of two), uniform across block
    if (good) {
        int m = min(cnt, CAP);
        n = 256;
        while (n < m) n <<= 1;
        for (int t = tid; t < n; t += 256)
            keys[t] = (t < m) ? d_cand[(size_t)pc * CAP + t] : 0ull;
    } else {
        // exact fallback: full strided scan for this (b,c)
        n = CAP;
        if (tid < NBIN) fh[tid] = 0;
        if (tid == 0) s_fc = 0;
        __syncthreads();
        const float* col = cls + ((size_t)b * N) * CC + c;
        for (int i = tid; i < N; i += 256) {
            float v = col[(size_t)i * CC];
            if (v > 0.01f) {
                int bin = (int)(v * 256.0f);
                bin = bin > 255 ? 255 : bin;
                atomicAdd(&fh[bin], 1);
            }
        }
        __syncthreads();
        if (tid == 0) {
            int acc = 0, l2 = 0;
            for (int s = NBIN - 1; s >= 0; s--) {
                acc += fh[s];
                if (acc >= TOPK) { l2 = s; break; }
            }
            s_flo = l2;
        }
        for (int t = tid; t < CAP; t += 256) keys[t] = 0ull;
        __syncthreads();
        float lof = (float)s_flo;
        for (int i = tid; i < N; i += 256) {
            float v = col[(size_t)i * CC];
            if (v > 0.01f && v * 256.0f >= lof) {
                int p = atomicAdd(&s_fc, 1);
                if (p < CAP)
                    keys[p] = ((unsigned long long)__float_as_uint(v) << 32) |
                              (unsigned long long)(unsigned)(~(unsigned)i);
            }
        }
    }
    __syncthreads();
    bitonic_sort_desc(keys, n, tid, 256);

    // top-200 candidate boxes
    if (tid < TOPK) {
        unsigned long long k = keys[tid];
        if (k) {
            int id = (int)~(unsigned)(k & 0xFFFFFFFFull);
            float4 bx = reinterpret_cast<const float4*>(boxes)[(size_t)b * N + id];
            sx1[tid] = bx.x; sy1[tid] = bx.y; sx2[tid] = bx.z; sy2[tid] = bx.w;
            sar[tid] = fmaxf(bx.z - bx.x, 0.0f) * fmaxf(bx.w - bx.y, 0.0f);
        } else {
            sx1[tid] = 1e30f; sy1[tid] = 1e30f; sx2[tid] = -1e30f; sy2[tid] = -1e30f;
            sar[tid] = 0.0f;
        }
    }
    __syncthreads();

    // suppression bitmask: row i holds bits j>i with IoU > 0.5
    if (tid < TOPK) {
        unsigned long long m0 = 0, m1 = 0, m2 = 0, m3 = 0;
        float x1 = sx1[tid], y1 = sy1[tid], x2 = sx2[tid], y2 = sy2[tid], a = sar[tid];
        for (int j = tid + 1; j < TOPK; j++) {
            float xx1 = fmaxf(x1, sx1[j]), yy1 = fmaxf(y1, sy1[j]);
            float xx2 = fminf(x2, sx2[j]), yy2 = fminf(y2, sy2[j]);
            float inter = fmaxf(xx2 - xx1, 0.0f) * fmaxf(yy2 - yy1, 0.0f);
            float uni = a + sar[j] - inter;
            float iou = inter / fmaxf(uni, 1e-8f);
            if (iou > 0.5f) {
                if (j < 64)       m0 |= 1ull << j;
                else if (j < 128) m1 |= 1ull << (j - 64);
                else if (j < 192) m2 |= 1ull << (j - 128);
                else              m3 |= 1ull << (j - 192);
            }
        }
        smask[tid * 4 + 0] = m0; smask[tid * 4 + 1] = m1;
        smask[tid * 4 + 2] = m2; smask[tid * 4 + 3] = m3;
    }
    __syncthreads();

    // greedy sweep (matches reference fori_loop exactly)
    if (tid == 0) {
        unsigned long long kw[4];
        for (int w = 0; w < 4; w++) {
            unsigned long long v = 0;
            for (int bit = 0; bit < 64; bit++) {
                int p = w * 64 + bit;
                if (p < TOPK && keys[p] != 0ull) v |= 1ull << bit;
            }
            kw[w] = v;
        }
        for (int i = 0; i < TOPK; i++) {
            if ((kw[i >> 6] >> (i & 63)) & 1ull) {
                kw[0] &= ~smask[i * 4 + 0];
                kw[1] &= ~smask[i * 4 + 1];
                kw[2] &= ~smask[i * 4 + 2];
                kw[3] &= ~smask[i * 4 + 3];
            }
        }
        skeep[0] = kw[0]; skeep[1] = kw[1]; skeep[2] = kw[2]; skeep[3] = kw[3];
    }
    __syncthreads();

    if (tid < TOPK) {
        unsigned long long k = keys[tid];
        bool kept = (k != 0ull) && (((skeep[tid >> 6] >> (tid & 63)) & 1ull) != 0ull);
        d_nms_s[pc * TOPK + tid] = kept ? __uint_as_float((unsigned)(k >> 32)) : neg_inf_f();
        d_nms_i[pc * TOPK + tid] = k ? (int)~(unsigned)(k & 0xFFFFFFFFull) : 0;
    }
}

// Merge stage 1: sort each 2048-entry third of the 6000 per-image pool, keep top-256.
__global__ __launch_bounds__(256) void k_merge1() {
    __shared__ unsigned long long buf[2048];
    int b = blockIdx.y, g = blockIdx.x, tid = threadIdx.x;
    const int TOT = CC * TOPK;  // 6000
    for (int t = tid; t < 2048; t += 256) {
        int pos = g * 2048 + t;
        unsigned long long k = 0ull;
        if (pos < TOT) {
            float s = d_nms_s[b * TOT + pos];
            if (s > 0.0f)
                k = ((unsigned long long)__float_as_uint(s) << 32) |
                    (unsigned long long)(8191 - pos);
        }
        buf[t] = k;
    }
    __syncthreads();
    bitonic_sort_desc(buf, 2048, tid, 256);
    if (tid < 256) d_top[b * 1024 + g * 256 + tid] = buf[tid];
}

// Merge stage 2: sort the 768 survivors, write top-100 detections.
__global__ __launch_bounds__(256) void k_merge2(const float* __restrict__ boxes,
                                                const float* __restrict__ rot,
                                                const float* __restrict__ tr,
                                                float* __restrict__ out, int N) {
    __shared__ unsigned long long top[1024];
    int b = blockIdx.x, tid = threadIdx.x;
    const int TOT = CC * TOPK;
    for (int t = tid; t < 1024; t += 256) top[t] = (t < 768) ? d_top[b * 1024 + t] : 0ull;
    __syncthreads();
    bitonic_sort_desc(top, 1024, tid, 256);

    const int SC_OFF = BB * MAXDET * 4;   // 6400
    const int LB_OFF = BB * MAXDET * 5;   // 8000
    const int RT_OFF = BB * MAXDET * 6;   // 9600
    const int TR_OFF = BB * MAXDET * 9;   // 14400

    if (tid < MAXDET) {
        int o = b * MAXDET + tid;
        unsigned long long k = top[tid];
        if (k) {
            float s = __uint_as_float((unsigned)(k >> 32));
            int pos = 8191 - (int)(unsigned)(k & 0xFFFFFFFFull);
            int c = pos / TOPK;
            int idx = d_nms_i[b * TOT + pos];
            float4 bx = reinterpret_cast<const float4*>(boxes)[(size_t)b * N + idx];
            out[o * 4 + 0] = bx.x; out[o * 4 + 1] = bx.y;
            out[o * 4 + 2] = bx.z; out[o * 4 + 3] = bx.w;
            out[SC_OFF + o] = s;
            out[LB_OFF + o] = (float)c;
            size_t rb = ((size_t)b * N + idx) * 3;
            out[RT_OFF + o * 3 + 0] = rot[rb + 0];
            out[RT_OFF + o * 3 + 1] = rot[rb + 1];
            out[RT_OFF + o * 3 + 2] = rot[rb + 2];
            out[TR_OFF + o * 3 + 0] = tr[rb + 0];
            out[TR_OFF + o * 3 + 1] = tr[rb + 1];
            out[TR_OFF + o * 3 + 2] = tr[rb + 2];
        } else {
            out[o * 4 + 0] = -1.0f; out[o * 4 + 1] = -1.0f;
            out[o * 4 + 2] = -1.0f; out[o * 4 + 3] = -1.0f;
            out[SC_OFF + o] = -1.0f;
            out[LB_OFF + o] = -1.0f;
            out[RT_OFF + o * 3 + 0] = -1.0f;
            out[RT_OFF + o * 3 + 1] = -1.0f;
            out[RT_OFF + o * 3 + 2] = -1.0f;
            out[TR_OFF + o * 3 + 0] = -1.0f;
            out[TR_OFF + o * 3 + 1] = -1.0f;
            out[TR_OFF + o * 3 + 2] = -1.0f;
        }
    }
}

// ---------------- launch ----------------
extern "C" void kernel_launch(void* const* d_in, const int* in_sizes, int n_in,
                              void* d_out, int out_size) {
    const float* boxes = (const float*)d_in[0];
    const float* cls   = (const float*)d_in[1];
    const float* rot   = (const float*)d_in[2];
    const float* tr    = (const float*)d_in[3];
    float* out = (float*)d_out;
    int N = in_sizes[0] / (BB * 4);

    k_zero<<<96, 256>>>();
    k_hist<<<dim3(8, BB), 512>>>(cls, N);
    k_thresh<<<2, 256>>>();
    k_collect<<<dim3(40, BB), 512>>>(cls, N);
    k_nms<<<BB * CC, 256>>>(cls, boxes, N);
    k_merge1<<<dim3(3, BB), 256>>>();
    k_merge2<<<BB, 256>>>(boxes, rot, tr, out, N);
}